// round 1
// baseline (speedup 1.0000x reference)
#include <cuda_runtime.h>
#include <cstdint>

// Problem constants
#define T_STEPS   16
#define BATCH     32
#define CHANS     256
#define HW        256           // H*W = 16*16
#define KLAG      4
#define TCTX      12            // T - K
#define SLICE     (BATCH*CHANS*HW)      // 2,097,152 elements per t
#define N_SPK     (T_STEPS*SLICE)       // 33,554,432
#define OFF_LOSS  (N_SPK)
#define OFF_LSP   (N_SPK + 1)
#define OFF_LSN   (N_SPK + 1 + TCTX*BATCH)
#define INV_CHW   (1.0f / 65536.0f)     // 1/(C*H*W)

// Scratch (device globals; no allocation allowed)
__device__ unsigned char g_ctx[TCTX * SLICE];     // binary context, t=0..11
__device__ float g_dpos[TCTX * BATCH];
__device__ float g_dneg[TCTX * BATCH];
__device__ int   g_inv[BATCH];

// ---------------------------------------------------------------------------
// Init: zero accumulators, build inverse permutation
// ---------------------------------------------------------------------------
__global__ void init_kernel(const int* __restrict__ rand_idx) {
    int tid = threadIdx.x;
    if (tid < TCTX * BATCH) { g_dpos[tid] = 0.f; g_dneg[tid] = 0.f; }
    if (tid < BATCH) g_inv[rand_idx[tid]] = tid;
}

// ---------------------------------------------------------------------------
// Scan + copy: copy spk_rec -> out, run leaky scan, write binary ctx (uint8)
// One thread per 4 consecutive elements (float4), looping over T.
// ---------------------------------------------------------------------------
__global__ __launch_bounds__(256) void scan_copy_kernel(
    const float* __restrict__ spk, float* __restrict__ out)
{
    const int i4 = blockIdx.x * blockDim.x + threadIdx.x;   // 0 .. SLICE/4-1
    const float4* __restrict__ spk4 = (const float4*)spk;
    float4* __restrict__ out4 = (float4*)out;

    float4 mem = make_float4(0.f, 0.f, 0.f, 0.f);

    #pragma unroll
    for (int t = 0; t < T_STEPS; t++) {
        size_t idx = (size_t)t * (SLICE/4) + i4;
        float4 x = spk4[idx];
        out4[idx] = x;
        if (t < TCTX) {
            float r0 = mem.x > 1.f ? 1.f : 0.f;
            float r1 = mem.y > 1.f ? 1.f : 0.f;
            float r2 = mem.z > 1.f ? 1.f : 0.f;
            float r3 = mem.w > 1.f ? 1.f : 0.f;
            mem.x = 0.5f * mem.x + x.x - r0;
            mem.y = 0.5f * mem.y + x.y - r1;
            mem.z = 0.5f * mem.z + x.z - r2;
            mem.w = 0.5f * mem.w + x.w - r3;
            uchar4 s;
            s.x = mem.x > 1.f;
            s.y = mem.y > 1.f;
            s.z = mem.z > 1.f;
            s.w = mem.w > 1.f;
            *(uchar4*)&g_ctx[(size_t)t * SLICE + (size_t)i4 * 4] = s;
        }
    }
}

// ---------------------------------------------------------------------------
// Fused GEMM + context reduction.
// For (t'=tt+4, b'): X[o,hw] = sum_c W[o,c]*spk[t',b',c,hw]  (256x256 GEMM)
//   dpos[tt,b']          += sum X .* ctx[tt, b']
//   dneg[tt,inv[b']]     += sum X .* ctx[tt, inv[b']]
// Block tile 128x128 (blockIdx.y in 0..3), 256 threads, 8x8 per thread.
// ---------------------------------------------------------------------------
__global__ __launch_bounds__(256) void gemm_reduce_kernel(
    const float* __restrict__ spk, const float* __restrict__ Wm)
{
    const int p  = blockIdx.x;        // 0..383
    const int tt = p >> 5;            // 0..11
    const int bp = p & 31;            // 0..31
    const int tp = tt + KLAG;         // 4..15
    const int q  = blockIdx.y;        // 0..3
    const int o0 = (q >> 1) * 128;
    const int h0 = (q & 1) * 128;

    __shared__ float Ws[16][132];     // Ws[c_local][o_local]
    __shared__ float Ss[16][132];     // Ss[c_local][hw_local]

    const int tid = threadIdx.x;
    const int tx  = tid & 15;
    const int ty  = tid >> 4;

    const float* __restrict__ Sb = spk + ((size_t)tp * BATCH + bp) * (CHANS * HW);

    float acc[8][8];
    #pragma unroll
    for (int i = 0; i < 8; i++)
        #pragma unroll
        for (int j = 0; j < 8; j++) acc[i][j] = 0.f;

    for (int c0 = 0; c0 < CHANS; c0 += 16) {
        // Load W tile: W[o0+o][c0+cc], transposed into Ws[cc][o]
        #pragma unroll
        for (int r = 0; r < 2; r++) {
            int idx = r * 256 + tid;          // 0..511
            int o   = idx >> 2;               // 0..127
            int cg  = (idx & 3) * 4;          // 0,4,8,12
            float4 v = *(const float4*)(Wm + (size_t)(o0 + o) * CHANS + c0 + cg);
            Ws[cg + 0][o] = v.x;
            Ws[cg + 1][o] = v.y;
            Ws[cg + 2][o] = v.z;
            Ws[cg + 3][o] = v.w;
        }
        // Load S tile: spk rows are hw-contiguous -> coalesced float4
        #pragma unroll
        for (int r = 0; r < 2; r++) {
            int idx = r * 256 + tid;
            int cc  = idx >> 5;               // 0..15
            int jg  = (idx & 31) * 4;         // 0..124
            float4 v = *(const float4*)(Sb + (size_t)(c0 + cc) * HW + h0 + jg);
            *(float4*)&Ss[cc][jg] = v;
        }
        __syncthreads();

        #pragma unroll
        for (int cc = 0; cc < 16; cc++) {
            float a[8], b[8];
            *(float4*)(a)     = *(const float4*)&Ws[cc][ty * 8];
            *(float4*)(a + 4) = *(const float4*)&Ws[cc][ty * 8 + 4];
            *(float4*)(b)     = *(const float4*)&Ss[cc][tx * 8];
            *(float4*)(b + 4) = *(const float4*)&Ss[cc][tx * 8 + 4];
            #pragma unroll
            for (int i = 0; i < 8; i++)
                #pragma unroll
                for (int j = 0; j < 8; j++)
                    acc[i][j] += a[i] * b[j];
        }
        __syncthreads();
    }

    // Epilogue: reduce X-tile against the two binary context slices
    const int bn = g_inv[bp];
    const unsigned char* __restrict__ cp =
        g_ctx + (((size_t)(tt * BATCH + bp) * CHANS + o0) * HW) + h0;
    const unsigned char* __restrict__ cn =
        g_ctx + (((size_t)(tt * BATCH + bn) * CHANS + o0) * HW) + h0;

    float pp = 0.f, pn = 0.f;
    #pragma unroll
    for (int i = 0; i < 8; i++) {
        int row = ty * 8 + i;
        uint2 up = *(const uint2*)(cp + (size_t)row * HW + tx * 8);
        uint2 un = *(const uint2*)(cn + (size_t)row * HW + tx * 8);
        #pragma unroll
        for (int j = 0; j < 8; j++) {
            unsigned int wp = (j < 4) ? up.x : up.y;
            unsigned int wn = (j < 4) ? un.x : un.y;
            float fp = (float)((wp >> ((j & 3) * 8)) & 0xffu);
            float fn = (float)((wn >> ((j & 3) * 8)) & 0xffu);
            pp += acc[i][j] * fp;
            pn += acc[i][j] * fn;
        }
    }

    // Warp reduce + one atomic per warp per target
    #pragma unroll
    for (int off = 16; off > 0; off >>= 1) {
        pp += __shfl_xor_sync(0xffffffffu, pp, off);
        pn += __shfl_xor_sync(0xffffffffu, pn, off);
    }
    if ((tid & 31) == 0) {
        atomicAdd(&g_dpos[tt * BATCH + bp], pp);
        atomicAdd(&g_dneg[tt * BATCH + bn], pn);
    }
}

// ---------------------------------------------------------------------------
// Finalize: scores -> log scores -> loss, written after the spk copy.
// One block, 384 threads (one per (t,b)).
// ---------------------------------------------------------------------------
__global__ void finalize_kernel(float* __restrict__ out) {
    __shared__ float shneg[TCTX * BATCH];
    __shared__ float shlsn[TCTX];
    __shared__ float shsum[TCTX * BATCH];
    const int tid = threadIdx.x;   // 0..383

    float lsp = logf(expf(g_dpos[tid] * INV_CHW) + 1e-4f);
    out[OFF_LSP + tid] = lsp;
    shneg[tid] = expf(g_dneg[tid] * INV_CHW) + 1e-4f;
    __syncthreads();

    if (tid < TCTX) {
        float s = 0.f;
        #pragma unroll
        for (int b = 0; b < BATCH; b++) s += shneg[tid * BATCH + b];
        float lsn = logf(s);
        shlsn[tid] = lsn;
        out[OFF_LSN + tid] = lsn;
    }
    __syncthreads();

    shsum[tid] = shlsn[tid >> 5] - lsp;
    __syncthreads();
    if (tid < 128) shsum[tid] = shsum[tid] + shsum[tid + 128] + shsum[tid + 256];
    __syncthreads();
    for (int off = 64; off > 0; off >>= 1) {
        if (tid < off) shsum[tid] += shsum[tid + off];
        __syncthreads();
    }
    if (tid == 0) out[OFF_LOSS] = shsum[0] * (1.0f / (TCTX * BATCH));
}

// ---------------------------------------------------------------------------
// Launch
// inputs: [0]=spk_rec fp32, [1]=mem_rec (unused), [2]=weight fp32 [C,C],
//         [3]=rand_idx int32 [B]
// ---------------------------------------------------------------------------
extern "C" void kernel_launch(void* const* d_in, const int* in_sizes, int n_in,
                              void* d_out, int out_size) {
    const float* spk  = (const float*)d_in[0];
    const float* Wm   = (const float*)d_in[2];
    const int*   ridx = (const int*)d_in[3];
    float* out = (float*)d_out;

    init_kernel<<<1, 384>>>(ridx);
    scan_copy_kernel<<<SLICE / 4 / 256, 256>>>(spk, out);
    gemm_reduce_kernel<<<dim3(TCTX * BATCH, 4), 256>>>(spk, Wm);
    finalize_kernel<<<1, 384>>>(out);
}

// round 3
// speedup vs baseline: 2.4607x; 2.4607x over previous
#include <cuda_runtime.h>
#include <cstdint>

// Problem constants
#define T_STEPS   16
#define BATCH     32
#define CHANS     256
#define HW        256           // H*W = 16*16
#define KLAG      4
#define TCTX      12            // T - K
#define SLICE     (BATCH*CHANS*HW)      // 2,097,152 elements per t
#define N_SPK     (T_STEPS*SLICE)       // 33,554,432
#define OFF_LOSS  (N_SPK)
#define OFF_LSP   (N_SPK + 1)
#define OFF_LSN   (N_SPK + 1 + TCTX*BATCH)
#define INV_CHW   (1.0f / 65536.0f)

// Scratch (device globals; no allocation allowed)
__device__ unsigned char g_ctx[TCTX * SLICE];     // binary context, t=0..11
__device__ float g_dpos[TCTX * BATCH];
__device__ float g_dneg[TCTX * BATCH];
__device__ int   g_inv[BATCH];

// ---------------------------------------------------------------------------
__global__ void init_kernel(const int* __restrict__ rand_idx) {
    int tid = threadIdx.x;
    if (tid < TCTX * BATCH) { g_dpos[tid] = 0.f; g_dneg[tid] = 0.f; }
    if (tid < BATCH) g_inv[rand_idx[tid]] = tid;
}

// ---------------------------------------------------------------------------
// Scan + copy: copy spk_rec -> out, run leaky scan, write binary ctx (uint8)
// ---------------------------------------------------------------------------
__global__ __launch_bounds__(256) void scan_copy_kernel(
    const float* __restrict__ spk, float* __restrict__ out)
{
    const int i4 = blockIdx.x * blockDim.x + threadIdx.x;   // 0 .. SLICE/4-1
    const float4* __restrict__ spk4 = (const float4*)spk;
    float4* __restrict__ out4 = (float4*)out;

    float4 mem = make_float4(0.f, 0.f, 0.f, 0.f);

    #pragma unroll
    for (int t = 0; t < T_STEPS; t++) {
        size_t idx = (size_t)t * (SLICE/4) + i4;
        float4 x = spk4[idx];
        out4[idx] = x;
        if (t < TCTX) {
            float r0 = mem.x > 1.f ? 1.f : 0.f;
            float r1 = mem.y > 1.f ? 1.f : 0.f;
            float r2 = mem.z > 1.f ? 1.f : 0.f;
            float r3 = mem.w > 1.f ? 1.f : 0.f;
            mem.x = 0.5f * mem.x + x.x - r0;
            mem.y = 0.5f * mem.y + x.y - r1;
            mem.z = 0.5f * mem.z + x.z - r2;
            mem.w = 0.5f * mem.w + x.w - r3;
            uchar4 s;
            s.x = mem.x > 1.f;
            s.y = mem.y > 1.f;
            s.z = mem.z > 1.f;
            s.w = mem.w > 1.f;
            *(uchar4*)&g_ctx[(size_t)t * SLICE + (size_t)i4 * 4] = s;
        }
    }
}

// ---------------------------------------------------------------------------
// TF32 tensor-core GEMM + context reduction.
// For (t'=tt+4, b'): X[o,hw] = sum_c W[o,c]*spk[t',b',c,hw]  (256x256x256)
// Epilogue reduces X against binary ctx (pos & neg) into scalar atomics.
// Block tile 128x128, 8 warps (2x4), warp tile 64x32, m16n8k8 tf32 MMA.
// ---------------------------------------------------------------------------
#define KC 32
#define WS_STRIDE 36    // 4*row+col distinct per lane -> conflict-free A loads
#define SS_STRIDE 136   // 8*row+col distinct per lane -> conflict-free B loads

__device__ __forceinline__ float f2tf32(float x) {
    uint32_t r;
    asm("cvt.rna.tf32.f32 %0, %1;" : "=r"(r) : "f"(x));
    return __uint_as_float(r);
}

__device__ __forceinline__ void mma_tf32(float* c, const uint32_t* a, const uint32_t* b) {
    asm volatile(
        "mma.sync.aligned.m16n8k8.row.col.f32.tf32.tf32.f32 "
        "{%0,%1,%2,%3}, {%4,%5,%6,%7}, {%8,%9}, {%0,%1,%2,%3};\n"
        : "+f"(c[0]), "+f"(c[1]), "+f"(c[2]), "+f"(c[3])
        : "r"(a[0]), "r"(a[1]), "r"(a[2]), "r"(a[3]), "r"(b[0]), "r"(b[1]));
}

__global__ __launch_bounds__(256) void gemm_reduce_kernel(
    const float* __restrict__ spk, const float* __restrict__ Wm)
{
    const int p  = blockIdx.x;        // 0..383
    const int tt = p >> 5;            // 0..11
    const int bp = p & 31;            // 0..31
    const int tp = tt + KLAG;         // 4..15
    const int q  = blockIdx.y;        // 0..3
    const int o0 = (q >> 1) * 128;
    const int h0 = (q & 1) * 128;

    __shared__ float Ws[128 * WS_STRIDE];   // A tile: [o 128][k 32]
    __shared__ float Ss[KC  * SS_STRIDE];   // B tile: [k 32][hw 128]

    const int tid  = threadIdx.x;
    const int wid  = tid >> 5;
    const int lane = tid & 31;
    const int gr   = lane >> 2;        // 0..7
    const int qq   = lane & 3;         // 0..3
    const int wm   = (wid & 1) * 64;   // warp m offset
    const int wn   = (wid >> 1) * 32;  // warp n offset

    const float* __restrict__ Sb = spk + ((size_t)tp * BATCH + bp) * (CHANS * HW);

    float acc[4][4][4];                // [m-frag][n-frag][c0..c3]
    #pragma unroll
    for (int i = 0; i < 4; i++)
        #pragma unroll
        for (int j = 0; j < 4; j++)
            #pragma unroll
            for (int r = 0; r < 4; r++) acc[i][j][r] = 0.f;

    for (int c0 = 0; c0 < CHANS; c0 += KC) {
        // Load W tile (128 rows x 32 k), cvt to tf32
        #pragma unroll
        for (int pass = 0; pass < 4; pass++) {
            int idx = pass * 256 + tid;     // 0..1023
            int row = idx >> 3;             // 0..127
            int cg  = (idx & 7) * 4;        // 0..28
            float4 v = *(const float4*)(Wm + (size_t)(o0 + row) * CHANS + c0 + cg);
            float* d = &Ws[row * WS_STRIDE + cg];
            d[0] = f2tf32(v.x); d[1] = f2tf32(v.y);
            d[2] = f2tf32(v.z); d[3] = f2tf32(v.w);
        }
        // Load S tile (32 k x 128 hw), cvt to tf32
        #pragma unroll
        for (int pass = 0; pass < 4; pass++) {
            int idx = pass * 256 + tid;     // 0..1023
            int cc  = idx >> 5;             // 0..31
            int jg  = (idx & 31) * 4;       // 0..124
            float4 v = *(const float4*)(Sb + (size_t)(c0 + cc) * HW + h0 + jg);
            float* d = &Ss[cc * SS_STRIDE + jg];
            d[0] = f2tf32(v.x); d[1] = f2tf32(v.y);
            d[2] = f2tf32(v.z); d[3] = f2tf32(v.w);
        }
        __syncthreads();

        #pragma unroll
        for (int ks = 0; ks < 4; ks++) {
            const int k0 = ks * 8;
            // B fragments: b0=(k=qq, n=gr), b1=(k=qq+4, n=gr)
            uint32_t bf[4][2];
            #pragma unroll
            for (int j = 0; j < 4; j++) {
                int n = wn + j * 8 + gr;
                bf[j][0] = __float_as_uint(Ss[(k0 + qq)     * SS_STRIDE + n]);
                bf[j][1] = __float_as_uint(Ss[(k0 + qq + 4) * SS_STRIDE + n]);
            }
            #pragma unroll
            for (int i = 0; i < 4; i++) {
                int r0 = wm + i * 16 + gr;
                uint32_t af[4];
                af[0] = __float_as_uint(Ws[(r0    ) * WS_STRIDE + k0 + qq]);
                af[1] = __float_as_uint(Ws[(r0 + 8) * WS_STRIDE + k0 + qq]);
                af[2] = __float_as_uint(Ws[(r0    ) * WS_STRIDE + k0 + qq + 4]);
                af[3] = __float_as_uint(Ws[(r0 + 8) * WS_STRIDE + k0 + qq + 4]);
                #pragma unroll
                for (int j = 0; j < 4; j++)
                    mma_tf32(acc[i][j], af, bf[j]);
            }
        }
        __syncthreads();
    }

    // Epilogue: reduce fragments against binary ctx slices (pos & neg)
    const int bn = g_inv[bp];
    const unsigned char* __restrict__ cp =
        g_ctx + (((size_t)(tt * BATCH + bp) * CHANS + o0) * HW) + h0;
    const unsigned char* __restrict__ cn =
        g_ctx + (((size_t)(tt * BATCH + bn) * CHANS + o0) * HW) + h0;

    float pp = 0.f, pn = 0.f;
    #pragma unroll
    for (int i = 0; i < 4; i++) {
        const int row0 = wm + i * 16 + gr;
        const int row1 = row0 + 8;
        #pragma unroll
        for (int j = 0; j < 4; j++) {
            const int col = wn + j * 8 + qq * 2;
            uchar2 p0 = *(const uchar2*)(cp + (size_t)row0 * HW + col);
            uchar2 p1 = *(const uchar2*)(cp + (size_t)row1 * HW + col);
            uchar2 n0 = *(const uchar2*)(cn + (size_t)row0 * HW + col);
            uchar2 n1 = *(const uchar2*)(cn + (size_t)row1 * HW + col);
            pp += acc[i][j][0] * (float)p0.x + acc[i][j][1] * (float)p0.y
                + acc[i][j][2] * (float)p1.x + acc[i][j][3] * (float)p1.y;
            pn += acc[i][j][0] * (float)n0.x + acc[i][j][1] * (float)n0.y
                + acc[i][j][2] * (float)n1.x + acc[i][j][3] * (float)n1.y;
        }
    }

    #pragma unroll
    for (int off = 16; off > 0; off >>= 1) {
        pp += __shfl_xor_sync(0xffffffffu, pp, off);
        pn += __shfl_xor_sync(0xffffffffu, pn, off);
    }
    if (lane == 0) {
        atomicAdd(&g_dpos[tt * BATCH + bp], pp);
        atomicAdd(&g_dneg[tt * BATCH + bn], pn);
    }
}

// ---------------------------------------------------------------------------
// Finalize: scores -> log scores -> loss
// ---------------------------------------------------------------------------
__global__ void finalize_kernel(float* __restrict__ out) {
    __shared__ float shneg[TCTX * BATCH];
    __shared__ float shlsn[TCTX];
    __shared__ float shsum[TCTX * BATCH];
    const int tid = threadIdx.x;   // 0..383

    float lsp = logf(expf(g_dpos[tid] * INV_CHW) + 1e-4f);
    out[OFF_LSP + tid] = lsp;
    shneg[tid] = expf(g_dneg[tid] * INV_CHW) + 1e-4f;
    __syncthreads();

    if (tid < TCTX) {
        float s = 0.f;
        #pragma unroll
        for (int b = 0; b < BATCH; b++) s += shneg[tid * BATCH + b];
        float lsn = logf(s);
        shlsn[tid] = lsn;
        out[OFF_LSN + tid] = lsn;
    }
    __syncthreads();

    shsum[tid] = shlsn[tid >> 5] - lsp;
    __syncthreads();
    if (tid < 128) shsum[tid] = shsum[tid] + shsum[tid + 128] + shsum[tid + 256];
    __syncthreads();
    for (int off = 64; off > 0; off >>= 1) {
        if (tid < off) shsum[tid] += shsum[tid + off];
        __syncthreads();
    }
    if (tid == 0) out[OFF_LOSS] = shsum[0] * (1.0f / (TCTX * BATCH));
}

// ---------------------------------------------------------------------------
extern "C" void kernel_launch(void* const* d_in, const int* in_sizes, int n_in,
                              void* d_out, int out_size) {
    const float* spk  = (const float*)d_in[0];
    const float* Wm   = (const float*)d_in[2];
    const int*   ridx = (const int*)d_in[3];
    float* out = (float*)d_out;

    init_kernel<<<1, 384>>>(ridx);
    scan_copy_kernel<<<SLICE / 4 / 256, 256>>>(spk, out);
    gemm_reduce_kernel<<<dim3(TCTX * BATCH, 4), 256>>>(spk, Wm);
    finalize_kernel<<<1, 384>>>(out);
}

// round 5
// speedup vs baseline: 4.3491x; 1.7674x over previous
#include <cuda_runtime.h>
#include <cuda_fp16.h>
#include <cstdint>

// Problem constants
#define T_STEPS   16
#define BATCH     32
#define CHANS     256
#define HW        256
#define KLAG      4
#define TCTX      12
#define SLICE     (BATCH*CHANS*HW)      // 2,097,152
#define N_SPK     (T_STEPS*SLICE)       // 33,554,432
#define OFF_LOSS  (N_SPK)
#define OFF_LSP   (N_SPK + 1)
#define OFF_LSN   (N_SPK + 1 + TCTX*BATCH)
#define INV_CHW   (1.0f / 65536.0f)

// Scratch (device globals)
__device__ unsigned char g_ctx[TCTX * SLICE];       // binary context (t=0..11)
__device__ __half        g_spk16[(size_t)TCTX * SLICE]; // fp16 spk slices t=4..15
__device__ __half        g_w16[CHANS * CHANS];
__device__ float g_dpos[TCTX * BATCH];
__device__ float g_dneg[TCTX * BATCH];
__device__ int   g_inv[BATCH];

// ---------------------------------------------------------------------------
__global__ void init_kernel(const int* __restrict__ rand_idx) {
    int tid = threadIdx.x;
    if (tid < TCTX * BATCH) { g_dpos[tid] = 0.f; g_dneg[tid] = 0.f; }
    if (tid < BATCH) g_inv[rand_idx[tid]] = tid;
}

// Convert W (fp32) -> fp16 once. 65536 elems, 64 blocks x 256 thr, 4 each.
__global__ void convw_kernel(const float* __restrict__ Wm) {
    int i = (blockIdx.x * 256 + threadIdx.x) * 4;
    float4 v = *(const float4*)(Wm + i);
    __half2 h01 = __floats2half2_rn(v.x, v.y);
    __half2 h23 = __floats2half2_rn(v.z, v.w);
    uint2 pk;
    pk.x = *(const uint32_t*)&h01;
    pk.y = *(const uint32_t*)&h23;
    *(uint2*)&g_w16[i] = pk;
}

// ---------------------------------------------------------------------------
// Scan + copy: copy spk_rec -> out, leaky scan -> binary ctx (uint8),
// and emit fp16 spk slices for t >= KLAG.
// ---------------------------------------------------------------------------
__global__ __launch_bounds__(256) void scan_copy_kernel(
    const float* __restrict__ spk, float* __restrict__ out)
{
    const int i4 = blockIdx.x * blockDim.x + threadIdx.x;   // 0 .. SLICE/4-1
    const float4* __restrict__ spk4 = (const float4*)spk;
    float4* __restrict__ out4 = (float4*)out;

    float4 mem = make_float4(0.f, 0.f, 0.f, 0.f);

    #pragma unroll
    for (int t = 0; t < T_STEPS; t++) {
        size_t idx = (size_t)t * (SLICE/4) + i4;
        float4 x = spk4[idx];
        out4[idx] = x;
        if (t >= KLAG) {
            __half2 h01 = __floats2half2_rn(x.x, x.y);
            __half2 h23 = __floats2half2_rn(x.z, x.w);
            uint2 pk;
            pk.x = *(const uint32_t*)&h01;
            pk.y = *(const uint32_t*)&h23;
            *(uint2*)&g_spk16[(size_t)(t - KLAG) * SLICE + (size_t)i4 * 4] = pk;
        }
        if (t < TCTX) {
            float r0 = mem.x > 1.f ? 1.f : 0.f;
            float r1 = mem.y > 1.f ? 1.f : 0.f;
            float r2 = mem.z > 1.f ? 1.f : 0.f;
            float r3 = mem.w > 1.f ? 1.f : 0.f;
            mem.x = 0.5f * mem.x + x.x - r0;
            mem.y = 0.5f * mem.y + x.y - r1;
            mem.z = 0.5f * mem.z + x.z - r2;
            mem.w = 0.5f * mem.w + x.w - r3;
            uchar4 s;
            s.x = mem.x > 1.f;
            s.y = mem.y > 1.f;
            s.z = mem.z > 1.f;
            s.w = mem.w > 1.f;
            *(uchar4*)&g_ctx[(size_t)t * SLICE + (size_t)i4 * 4] = s;
        }
    }
}

// ---------------------------------------------------------------------------
// FP16 tensor-core GEMM (m16n8k16 + ldmatrix) + context reduction.
// Block tile 128(o) x 128(hw), K=256 in chunks of 64. 8 warps (2x4),
// warp tile 64x32.
// ---------------------------------------------------------------------------
#define KC 64
#define AS_STRIDE 72    // fp16 elems: 144B row stride -> +1 16B-group per row
#define BS_STRIDE 136   // fp16 elems: 272B row stride -> +1 16B-group per row

__device__ __forceinline__ uint32_t smem_u32(const void* p) {
    return (uint32_t)__cvta_generic_to_shared(p);
}
__device__ __forceinline__ void ldsm_x4(uint32_t* r, uint32_t a) {
    asm volatile("ldmatrix.sync.aligned.m8n8.x4.shared.b16 {%0,%1,%2,%3}, [%4];"
        : "=r"(r[0]), "=r"(r[1]), "=r"(r[2]), "=r"(r[3]) : "r"(a));
}
__device__ __forceinline__ void ldsm_x4_t(uint32_t* r, uint32_t a) {
    asm volatile("ldmatrix.sync.aligned.m8n8.x4.trans.shared.b16 {%0,%1,%2,%3}, [%4];"
        : "=r"(r[0]), "=r"(r[1]), "=r"(r[2]), "=r"(r[3]) : "r"(a));
}
__device__ __forceinline__ void mma_fp16(float* c, const uint32_t* a, const uint32_t* b) {
    asm volatile(
        "mma.sync.aligned.m16n8k16.row.col.f32.f16.f16.f32 "
        "{%0,%1,%2,%3}, {%4,%5,%6,%7}, {%8,%9}, {%0,%1,%2,%3};\n"
        : "+f"(c[0]), "+f"(c[1]), "+f"(c[2]), "+f"(c[3])
        : "r"(a[0]), "r"(a[1]), "r"(a[2]), "r"(a[3]), "r"(b[0]), "r"(b[1]));
}

__global__ __launch_bounds__(256) void gemm_reduce_kernel()
{
    const int p  = blockIdx.x;        // 0..383
    const int tt = p >> 5;            // 0..11
    const int bp = p & 31;            // 0..31
    const int q  = blockIdx.y;        // 0..3
    const int o0 = (q >> 1) * 128;
    const int h0 = (q & 1) * 128;

    __shared__ __align__(16) __half As[128 * AS_STRIDE]; // [o][k]
    __shared__ __align__(16) __half Bs[KC  * BS_STRIDE]; // [k][hw]

    const int tid  = threadIdx.x;
    const int wid  = tid >> 5;
    const int lane = tid & 31;
    const int gr   = lane >> 2;
    const int qq   = lane & 3;
    const int wm   = (wid & 1) * 64;
    const int wn   = (wid >> 1) * 32;
    const int lrow = lane & 15;
    const int lcol = (lane >> 4) * 8;

    const __half* __restrict__ Sb = g_spk16 + ((size_t)tt * BATCH + bp) * (CHANS * HW);
    const __half* __restrict__ Wb = g_w16 + (size_t)o0 * CHANS;

    float acc[4][4][4];
    #pragma unroll
    for (int i = 0; i < 4; i++)
        #pragma unroll
        for (int j = 0; j < 4; j++)
            #pragma unroll
            for (int r = 0; r < 4; r++) acc[i][j][r] = 0.f;

    for (int c0 = 0; c0 < CHANS; c0 += KC) {
        // Fill A: 128 rows x 64 k fp16 (8 uint4-chunks per row)
        #pragma unroll
        for (int ps = 0; ps < 4; ps++) {
            int idx = ps * 256 + tid;       // 0..1023
            int row = idx >> 3;             // 0..127
            int ch  = (idx & 7) * 8;        // fp16 col 0..56
            uint4 v = *(const uint4*)(Wb + (size_t)row * CHANS + c0 + ch);
            *(uint4*)&As[row * AS_STRIDE + ch] = v;
        }
        // Fill B: 64 k rows x 128 hw fp16 (16 uint4-chunks per row)
        #pragma unroll
        for (int ps = 0; ps < 4; ps++) {
            int idx = ps * 256 + tid;
            int row = idx >> 4;             // 0..63
            int ch  = (idx & 15) * 8;       // 0..120
            uint4 v = *(const uint4*)(Sb + (size_t)(c0 + row) * HW + h0 + ch);
            *(uint4*)&Bs[row * BS_STRIDE + ch] = v;
        }
        __syncthreads();

        #pragma unroll
        for (int ks = 0; ks < 4; ks++) {
            const int kb = ks * 16;
            uint32_t af[4][4];
            #pragma unroll
            for (int i = 0; i < 4; i++)
                ldsm_x4(af[i], smem_u32(&As[(wm + i * 16 + lrow) * AS_STRIDE + kb + lcol]));
            uint32_t bf[2][4];
            #pragma unroll
            for (int jj = 0; jj < 2; jj++)
                ldsm_x4_t(bf[jj], smem_u32(&Bs[(kb + lrow) * BS_STRIDE + wn + jj * 16 + lcol]));
            #pragma unroll
            for (int i = 0; i < 4; i++)
                #pragma unroll
                for (int j = 0; j < 4; j++)
                    mma_fp16(acc[i][j], af[i], &bf[j >> 1][(j & 1) * 2]);
        }
        __syncthreads();
    }

    // Epilogue: reduce fragments against binary ctx slices (pos & neg)
    const int bn = g_inv[bp];
    const unsigned char* __restrict__ cp =
        g_ctx + (((size_t)(tt * BATCH + bp) * CHANS + o0) * HW) + h0;
    const unsigned char* __restrict__ cn =
        g_ctx + (((size_t)(tt * BATCH + bn) * CHANS + o0) * HW) + h0;

    float pp = 0.f, pn = 0.f;
    #pragma unroll
    for (int i = 0; i < 4; i++) {
        const int row0 = wm + i * 16 + gr;
        const int row1 = row0 + 8;
        #pragma unroll
        for (int j = 0; j < 4; j++) {
            const int col = wn + j * 8 + qq * 2;
            uchar2 p0 = *(const uchar2*)(cp + (size_t)row0 * HW + col);
            uchar2 p1 = *(const uchar2*)(cp + (size_t)row1 * HW + col);
            uchar2 n0 = *(const uchar2*)(cn + (size_t)row0 * HW + col);
            uchar2 n1 = *(const uchar2*)(cn + (size_t)row1 * HW + col);
            pp += acc[i][j][0] * (float)p0.x + acc[i][j][1] * (float)p0.y
                + acc[i][j][2] * (float)p1.x + acc[i][j][3] * (float)p1.y;
            pn += acc[i][j][0] * (float)n0.x + acc[i][j][1] * (float)n0.y
                + acc[i][j][2] * (float)n1.x + acc[i][j][3] * (float)n1.y;
        }
    }

    #pragma unroll
    for (int off = 16; off > 0; off >>= 1) {
        pp += __shfl_xor_sync(0xffffffffu, pp, off);
        pn += __shfl_xor_sync(0xffffffffu, pn, off);
    }
    if (lane == 0) {
        atomicAdd(&g_dpos[tt * BATCH + bp], pp);
        atomicAdd(&g_dneg[tt * BATCH + bn], pn);
    }
}

// ---------------------------------------------------------------------------
__global__ void finalize_kernel(float* __restrict__ out) {
    __shared__ float shneg[TCTX * BATCH];
    __shared__ float shlsn[TCTX];
    __shared__ float shsum[TCTX * BATCH];
    const int tid = threadIdx.x;   // 0..383

    float lsp = logf(expf(g_dpos[tid] * INV_CHW) + 1e-4f);
    out[OFF_LSP + tid] = lsp;
    shneg[tid] = expf(g_dneg[tid] * INV_CHW) + 1e-4f;
    __syncthreads();

    if (tid < TCTX) {
        float s = 0.f;
        #pragma unroll
        for (int b = 0; b < BATCH; b++) s += shneg[tid * BATCH + b];
        float lsn = logf(s);
        shlsn[tid] = lsn;
        out[OFF_LSN + tid] = lsn;
    }
    __syncthreads();

    shsum[tid] = shlsn[tid >> 5] - lsp;
    __syncthreads();
    if (tid < 128) shsum[tid] = shsum[tid] + shsum[tid + 128] + shsum[tid + 256];
    __syncthreads();
    for (int off = 64; off > 0; off >>= 1) {
        if (tid < off) shsum[tid] += shsum[tid + off];
        __syncthreads();
    }
    if (tid == 0) out[OFF_LOSS] = shsum[0] * (1.0f / (TCTX * BATCH));
}

// ---------------------------------------------------------------------------
extern "C" void kernel_launch(void* const* d_in, const int* in_sizes, int n_in,
                              void* d_out, int out_size) {
    const float* spk  = (const float*)d_in[0];
    const float* Wm   = (const float*)d_in[2];
    const int*   ridx = (const int*)d_in[3];
    float* out = (float*)d_out;

    init_kernel<<<1, 384>>>(ridx);
    convw_kernel<<<64, 256>>>(Wm);
    scan_copy_kernel<<<SLICE / 4 / 256, 256>>>(spk, out);
    gemm_reduce_kernel<<<dim3(TCTX * BATCH, 4), 256>>>();
    finalize_kernel<<<1, 384>>>(out);
}

// round 6
// speedup vs baseline: 4.6267x; 1.0638x over previous
#include <cuda_runtime.h>
#include <cuda_fp16.h>
#include <cstdint>

// Problem constants
#define T_STEPS   16
#define BATCH     32
#define CHANS     256
#define HW        256
#define KLAG      4
#define TCTX      12
#define SLICE     (BATCH*CHANS*HW)      // 2,097,152
#define N_SPK     (T_STEPS*SLICE)       // 33,554,432
#define OFF_LOSS  (N_SPK)
#define OFF_LSP   (N_SPK + 1)
#define OFF_LSN   (N_SPK + 1 + TCTX*BATCH)
#define INV_CHW   (1.0f / 65536.0f)

// Scratch (device globals)
__device__ unsigned char g_ctx[TCTX * SLICE];            // binary context (t=0..11)
__device__ __half        g_spk16[(size_t)TCTX * SLICE];  // fp16 spk slices t=4..15
__device__ __half        g_w16[CHANS * CHANS];
__device__ float g_dpos[TCTX * BATCH];
__device__ float g_dneg[TCTX * BATCH];
__device__ int   g_inv[BATCH];

// ---------------------------------------------------------------------------
__global__ void init_kernel(const int* __restrict__ rand_idx) {
    int tid = threadIdx.x;
    if (tid < TCTX * BATCH) { g_dpos[tid] = 0.f; g_dneg[tid] = 0.f; }
    if (tid < BATCH) g_inv[rand_idx[tid]] = tid;
}

// Convert W (fp32) -> fp16 once.
__global__ void convw_kernel(const float* __restrict__ Wm) {
    int i = (blockIdx.x * 256 + threadIdx.x) * 4;
    float4 v = *(const float4*)(Wm + i);
    __half2 h01 = __floats2half2_rn(v.x, v.y);
    __half2 h23 = __floats2half2_rn(v.z, v.w);
    uint2 pk;
    pk.x = *(const uint32_t*)&h01;
    pk.y = *(const uint32_t*)&h23;
    *(uint2*)&g_w16[i] = pk;
}

// ---------------------------------------------------------------------------
// Scan + copy: copy spk_rec -> out, leaky scan -> binary ctx (uint8),
// and emit fp16 spk slices for t >= KLAG.
// ---------------------------------------------------------------------------
__global__ __launch_bounds__(256) void scan_copy_kernel(
    const float* __restrict__ spk, float* __restrict__ out)
{
    const int i4 = blockIdx.x * blockDim.x + threadIdx.x;   // 0 .. SLICE/4-1
    const float4* __restrict__ spk4 = (const float4*)spk;
    float4* __restrict__ out4 = (float4*)out;

    float4 mem = make_float4(0.f, 0.f, 0.f, 0.f);

    #pragma unroll
    for (int t = 0; t < T_STEPS; t++) {
        size_t idx = (size_t)t * (SLICE/4) + i4;
        float4 x = spk4[idx];
        out4[idx] = x;
        if (t >= KLAG) {
            __half2 h01 = __floats2half2_rn(x.x, x.y);
            __half2 h23 = __floats2half2_rn(x.z, x.w);
            uint2 pk;
            pk.x = *(const uint32_t*)&h01;
            pk.y = *(const uint32_t*)&h23;
            *(uint2*)&g_spk16[(size_t)(t - KLAG) * SLICE + (size_t)i4 * 4] = pk;
        }
        if (t < TCTX) {
            float r0 = mem.x > 1.f ? 1.f : 0.f;
            float r1 = mem.y > 1.f ? 1.f : 0.f;
            float r2 = mem.z > 1.f ? 1.f : 0.f;
            float r3 = mem.w > 1.f ? 1.f : 0.f;
            mem.x = 0.5f * mem.x + x.x - r0;
            mem.y = 0.5f * mem.y + x.y - r1;
            mem.z = 0.5f * mem.z + x.z - r2;
            mem.w = 0.5f * mem.w + x.w - r3;
            uchar4 s;
            s.x = mem.x > 1.f;
            s.y = mem.y > 1.f;
            s.z = mem.z > 1.f;
            s.w = mem.w > 1.f;
            *(uchar4*)&g_ctx[(size_t)t * SLICE + (size_t)i4 * 4] = s;
        }
    }
}

// ---------------------------------------------------------------------------
// FP16 tensor-core GEMM (m16n8k16 + ldmatrix) with cp.async 2-stage pipeline.
// Block tile 128(o) x 128(hw), K=256 in chunks of 32. 8 warps (2x4),
// warp tile 64x32.
// ---------------------------------------------------------------------------
#define KC 32
#define AS_STRIDE 40    // fp16: 80B/row = 5 groups -> rows hit 8 distinct groups
#define BS_STRIDE 136   // fp16: 272B/row = 17 groups -> conflict-free

__device__ __forceinline__ uint32_t smem_u32(const void* p) {
    return (uint32_t)__cvta_generic_to_shared(p);
}
__device__ __forceinline__ void cp16(uint32_t dst, const void* src) {
    asm volatile("cp.async.cg.shared.global [%0], [%1], 16;" :: "r"(dst), "l"(src));
}
__device__ __forceinline__ void cp_commit() {
    asm volatile("cp.async.commit_group;");
}
template<int N> __device__ __forceinline__ void cp_wait() {
    asm volatile("cp.async.wait_group %0;" :: "n"(N));
}
__device__ __forceinline__ void ldsm_x4(uint32_t* r, uint32_t a) {
    asm volatile("ldmatrix.sync.aligned.m8n8.x4.shared.b16 {%0,%1,%2,%3}, [%4];"
        : "=r"(r[0]), "=r"(r[1]), "=r"(r[2]), "=r"(r[3]) : "r"(a));
}
__device__ __forceinline__ void ldsm_x4_t(uint32_t* r, uint32_t a) {
    asm volatile("ldmatrix.sync.aligned.m8n8.x4.trans.shared.b16 {%0,%1,%2,%3}, [%4];"
        : "=r"(r[0]), "=r"(r[1]), "=r"(r[2]), "=r"(r[3]) : "r"(a));
}
__device__ __forceinline__ void mma_fp16(float* c, const uint32_t* a, const uint32_t* b) {
    asm volatile(
        "mma.sync.aligned.m16n8k16.row.col.f32.f16.f16.f32 "
        "{%0,%1,%2,%3}, {%4,%5,%6,%7}, {%8,%9}, {%0,%1,%2,%3};\n"
        : "+f"(c[0]), "+f"(c[1]), "+f"(c[2]), "+f"(c[3])
        : "r"(a[0]), "r"(a[1]), "r"(a[2]), "r"(a[3]), "r"(b[0]), "r"(b[1]));
}

__global__ __launch_bounds__(256) void gemm_reduce_kernel()
{
    const int p  = blockIdx.x;        // 0..383
    const int tt = p >> 5;            // 0..11
    const int bp = p & 31;            // 0..31
    const int q  = blockIdx.y;        // 0..3
    const int o0 = (q >> 1) * 128;
    const int h0 = (q & 1) * 128;

    __shared__ __align__(16) __half As[2][128 * AS_STRIDE]; // [buf][o][k]
    __shared__ __align__(16) __half Bs[2][KC  * BS_STRIDE]; // [buf][k][hw]

    const int tid  = threadIdx.x;
    const int wid  = tid >> 5;
    const int lane = tid & 31;
    const int gr   = lane >> 2;
    const int qq   = lane & 3;
    const int wm   = (wid & 1) * 64;
    const int wn   = (wid >> 1) * 32;
    const int lrow = lane & 15;
    const int lcol = (lane >> 4) * 8;

    const __half* __restrict__ Sb = g_spk16 + ((size_t)tt * BATCH + bp) * (CHANS * HW);
    const __half* __restrict__ Wb = g_w16 + (size_t)o0 * CHANS;

    // Per-thread fill coordinates (2 x 16B for A, 2 x 16B for B per chunk)
    const int a_row0 = tid >> 2;                 // 0..63
    const int a_ch   = (tid & 3) * 8;            // 0,8,16,24
    const int b_row0 = tid >> 4;                 // 0..15
    const int b_ch   = (tid & 15) * 8;           // 0..120

    float acc[4][4][4];
    #pragma unroll
    for (int i = 0; i < 4; i++)
        #pragma unroll
        for (int j = 0; j < 4; j++)
            #pragma unroll
            for (int r = 0; r < 4; r++) acc[i][j][r] = 0.f;

    // ---- pipelined fill helper (inlined manually) ----
    #define FILL_STAGE(c0, buf)                                                 \
        do {                                                                    \
            cp16(smem_u32(&As[buf][(a_row0      ) * AS_STRIDE + a_ch]),         \
                 Wb + (size_t)(a_row0      ) * CHANS + (c0) + a_ch);            \
            cp16(smem_u32(&As[buf][(a_row0 + 64 ) * AS_STRIDE + a_ch]),         \
                 Wb + (size_t)(a_row0 + 64 ) * CHANS + (c0) + a_ch);            \
            cp16(smem_u32(&Bs[buf][(b_row0      ) * BS_STRIDE + b_ch]),         \
                 Sb + (size_t)((c0) + b_row0      ) * HW + h0 + b_ch);          \
            cp16(smem_u32(&Bs[buf][(b_row0 + 16 ) * BS_STRIDE + b_ch]),         \
                 Sb + (size_t)((c0) + b_row0 + 16 ) * HW + h0 + b_ch);          \
            cp_commit();                                                        \
        } while (0)

    FILL_STAGE(0, 0);

    #pragma unroll
    for (int c = 0; c < 8; c++) {
        const int buf = c & 1;
        if (c < 7) {
            FILL_STAGE((c + 1) * KC, (c + 1) & 1);
            cp_wait<1>();
        } else {
            cp_wait<0>();
        }
        __syncthreads();

        #pragma unroll
        for (int ks = 0; ks < 2; ks++) {
            const int kb = ks * 16;
            uint32_t af[4][4];
            #pragma unroll
            for (int i = 0; i < 4; i++)
                ldsm_x4(af[i], smem_u32(&As[buf][(wm + i * 16 + lrow) * AS_STRIDE + kb + lcol]));
            uint32_t bf[2][4];
            #pragma unroll
            for (int jj = 0; jj < 2; jj++)
                ldsm_x4_t(bf[jj], smem_u32(&Bs[buf][(kb + lrow) * BS_STRIDE + wn + jj * 16 + lcol]));
            #pragma unroll
            for (int i = 0; i < 4; i++)
                #pragma unroll
                for (int j = 0; j < 4; j++)
                    mma_fp16(acc[i][j], af[i], &bf[j >> 1][(j & 1) * 2]);
        }
        __syncthreads();
    }

    // Epilogue: reduce fragments against binary ctx slices (pos & neg)
    const int bn = g_inv[bp];
    const unsigned char* __restrict__ cp_ =
        g_ctx + (((size_t)(tt * BATCH + bp) * CHANS + o0) * HW) + h0;
    const unsigned char* __restrict__ cn_ =
        g_ctx + (((size_t)(tt * BATCH + bn) * CHANS + o0) * HW) + h0;

    float pp = 0.f, pn = 0.f;
    #pragma unroll
    for (int i = 0; i < 4; i++) {
        const int row0 = wm + i * 16 + gr;
        const int row1 = row0 + 8;
        #pragma unroll
        for (int j = 0; j < 4; j++) {
            const int col = wn + j * 8 + qq * 2;
            uchar2 p0 = *(const uchar2*)(cp_ + (size_t)row0 * HW + col);
            uchar2 p1 = *(const uchar2*)(cp_ + (size_t)row1 * HW + col);
            uchar2 n0 = *(const uchar2*)(cn_ + (size_t)row0 * HW + col);
            uchar2 n1 = *(const uchar2*)(cn_ + (size_t)row1 * HW + col);
            pp += acc[i][j][0] * (float)p0.x + acc[i][j][1] * (float)p0.y
                + acc[i][j][2] * (float)p1.x + acc[i][j][3] * (float)p1.y;
            pn += acc[i][j][0] * (float)n0.x + acc[i][j][1] * (float)n0.y
                + acc[i][j][2] * (float)n1.x + acc[i][j][3] * (float)n1.y;
        }
    }

    #pragma unroll
    for (int off = 16; off > 0; off >>= 1) {
        pp += __shfl_xor_sync(0xffffffffu, pp, off);
        pn += __shfl_xor_sync(0xffffffffu, pn, off);
    }
    if (lane == 0) {
        atomicAdd(&g_dpos[tt * BATCH + bp], pp);
        atomicAdd(&g_dneg[tt * BATCH + bn], pn);
    }
}

// ---------------------------------------------------------------------------
__global__ void finalize_kernel(float* __restrict__ out) {
    __shared__ float shneg[TCTX * BATCH];
    __shared__ float shlsn[TCTX];
    __shared__ float shsum[TCTX * BATCH];
    const int tid = threadIdx.x;   // 0..383

    float lsp = logf(expf(g_dpos[tid] * INV_CHW) + 1e-4f);
    out[OFF_LSP + tid] = lsp;
    shneg[tid] = expf(g_dneg[tid] * INV_CHW) + 1e-4f;
    __syncthreads();

    if (tid < TCTX) {
        float s = 0.f;
        #pragma unroll
        for (int b = 0; b < BATCH; b++) s += shneg[tid * BATCH + b];
        float lsn = logf(s);
        shlsn[tid] = lsn;
        out[OFF_LSN + tid] = lsn;
    }
    __syncthreads();

    shsum[tid] = shlsn[tid >> 5] - lsp;
    __syncthreads();
    if (tid < 128) shsum[tid] = shsum[tid] + shsum[tid + 128] + shsum[tid + 256];
    __syncthreads();
    for (int off = 64; off > 0; off >>= 1) {
        if (tid < off) shsum[tid] += shsum[tid + off];
        __syncthreads();
    }
    if (tid == 0) out[OFF_LOSS] = shsum[0] * (1.0f / (TCTX * BATCH));
}

// ---------------------------------------------------------------------------
extern "C" void kernel_launch(void* const* d_in, const int* in_sizes, int n_in,
                              void* d_out, int out_size) {
    const float* spk  = (const float*)d_in[0];
    const float* Wm   = (const float*)d_in[2];
    const int*   ridx = (const int*)d_in[3];
    float* out = (float*)d_out;

    init_kernel<<<1, 384>>>(ridx);
    convw_kernel<<<64, 256>>>(Wm);
    scan_copy_kernel<<<SLICE / 4 / 256, 256>>>(spk, out);
    gemm_reduce_kernel<<<dim3(TCTX * BATCH, 4), 256>>>();
    finalize_kernel<<<1, 384>>>(out);
}